// round 12
// baseline (speedup 1.0000x reference)
#include <cuda_runtime.h>
#include <cuda_bf16.h>
#include <cstdint>
#include <cstddef>
#include <type_traits>

#define NTOK 2048
#define DM   1024
#define DI   2048
#define DS   16
#define LSEQ 1024

// per-tensor fp8 scales (power of 2)
#define S_XN   32.f
#define S_W    1024.f
#define S_XC   1024.f
#define S_G    4096.f
#define DESC0  (1.f / (S_XN * S_W))
#define DESC1  (1.f / (S_XC * S_W))
#define DESC2  (1.f / (S_G * S_W))

typedef unsigned long long ull;

// ------------------------- scratch -------------------------
__device__ float g_xbr[NTOK * DI];                 // x_branch fp32 (conv input)
__device__ __nv_bfloat16 g_sg[NTOK * DI];          // silu(gate) bf16
__device__ float g_xc[NTOK * DI];                  // conv+silu fp32
__device__ float g_dt[NTOK * DI];
__device__ float g_Bp[NTOK * DS];
__device__ float g_Cp[NTOK * DS];

__device__ uint8_t g_xn8[NTOK * DM];               // e4m3 operands
__device__ uint8_t g_xc8[NTOK * DI];
__device__ uint8_t g_g8[NTOK * DI];
__device__ uint8_t g_Win8[2 * DI * DM];
__device__ uint8_t g_Wdt8[DI * DI];
__device__ uint8_t g_Wout8[DM * DI];

// ------------------------- PTX helpers -------------------------
__device__ __forceinline__ uint32_t cvta_s(const void* p) {
    uint32_t a;
    asm("{.reg .u64 t; cvta.to.shared.u64 t, %1; cvt.u32.u64 %0, t;}" : "=r"(a) : "l"(p));
    return a;
}
__device__ __forceinline__ void cp_async16(uint32_t saddr, const void* gaddr) {
    asm volatile("cp.async.cg.shared.global [%0], [%1], 16;" :: "r"(saddr), "l"(gaddr));
}
#define CP_COMMIT() asm volatile("cp.async.commit_group;" ::: "memory")
#define CP_WAIT(n)  asm volatile("cp.async.wait_group %0;" :: "n"(n) : "memory")

__device__ __forceinline__ void ldsm4(uint32_t* r, uint32_t addr) {
    asm volatile("ldmatrix.sync.aligned.m8n8.x4.shared.b16 {%0,%1,%2,%3}, [%4];"
                 : "=r"(r[0]), "=r"(r[1]), "=r"(r[2]), "=r"(r[3]) : "r"(addr));
}
__device__ __forceinline__ void mma_fp8(float* c, const uint32_t* a, const uint32_t* b) {
    asm volatile("mma.sync.aligned.m16n8k32.row.col.f32.e4m3.e4m3.f32 "
                 "{%0,%1,%2,%3},{%4,%5,%6,%7},{%8,%9},{%0,%1,%2,%3};"
                 : "+f"(c[0]), "+f"(c[1]), "+f"(c[2]), "+f"(c[3])
                 : "r"(a[0]), "r"(a[1]), "r"(a[2]), "r"(a[3]), "r"(b[0]), "r"(b[1]));
}
// byte0 = lo, byte1 = hi
__device__ __forceinline__ uint32_t qe4x2(float hi, float lo) {
    uint16_t r;
    asm("cvt.rn.satfinite.e4m3x2.f32 %0, %1, %2;" : "=h"(r) : "f"(hi), "f"(lo));
    return (uint32_t)r;
}

__device__ __forceinline__ ull pk2(float lo, float hi) {
    ull r; asm("mov.b64 %0,{%1,%2};" : "=l"(r) : "f"(lo), "f"(hi)); return r;
}
__device__ __forceinline__ float2 upk2(ull v) {
    float2 f; asm("mov.b64 {%0,%1},%2;" : "=f"(f.x), "=f"(f.y) : "l"(v)); return f;
}
__device__ __forceinline__ ull fma2_(ull a, ull b, ull c) {
    ull d; asm("fma.rn.f32x2 %0,%1,%2,%3;" : "=l"(d) : "l"(a), "l"(b), "l"(c)); return d;
}
__device__ __forceinline__ ull mul2_(ull a, ull b) {
    ull d; asm("mul.rn.f32x2 %0,%1,%2;" : "=l"(d) : "l"(a), "l"(b)); return d;
}
__device__ __forceinline__ float ex2_(float x) {
    float y; asm("ex2.approx.f32 %0,%1;" : "=f"(y) : "f"(x)); return y;
}

#define MBAR_INIT(addr, cnt) \
    asm volatile("mbarrier.init.shared.b64 [%0], %1;" :: "r"(addr), "r"(cnt) : "memory")

#define MBAR_WAIT_CLU(addr, par) do {                                               \
    uint32_t _m = (addr); uint32_t _p = (par); uint32_t _d;                         \
    asm volatile("{\n\t.reg .pred p;\n\t"                                           \
        "mbarrier.try_wait.parity.acquire.cluster.shared::cta.b64 p, [%1], %2;\n\t" \
        "selp.b32 %0,1,0,p;\n\t}" : "=r"(_d) : "r"(_m), "r"(_p) : "memory");        \
    if (!_d) {                                                                      \
        asm volatile("{\n\t.reg .pred P1;\n\t"                                      \
        "WLC_%=:\n\t"                                                               \
        "mbarrier.try_wait.parity.acquire.cluster.shared::cta.b64 P1, [%0], %1, 0x989680;\n\t" \
        "@P1 bra.uni WDC_%=;\n\t"                                                   \
        "bra.uni WLC_%=;\n\t"                                                       \
        "WDC_%=:\n\t}" :: "r"(_m), "r"(_p) : "memory");                             \
    } } while (0)

#define ST_REMOTE_F32(laddr, rnk, val) \
    asm volatile("{.reg .b32 ra; mapa.shared::cluster.u32 ra, %0, %1;" \
                 " st.shared::cluster.f32 [ra], %2;}" \
                 :: "r"(laddr), "r"(rnk), "f"(val) : "memory")

#define MBAR_ARRIVE_REMOTE(laddr, rnk) \
    asm volatile("{.reg .b32 ra; mapa.shared::cluster.u32 ra, %0, %1;" \
                 " mbarrier.arrive.shared::cluster.b64 _, [ra];}" \
                 :: "r"(laddr), "r"(rnk) : "memory")

// ------------------------- fp32 -> e4m3 weight conversion (x S_W) -------------------------
__global__ void cvt_w8_kernel(const float* __restrict__ src, uint8_t* __restrict__ q, int n8)
{
    int i = blockIdx.x * blockDim.x + threadIdx.x;
    if (i >= n8) return;
    float4 a = reinterpret_cast<const float4*>(src)[2 * i];
    float4 b = reinterpret_cast<const float4*>(src)[2 * i + 1];
    uint2 o;
    o.x = qe4x2(a.y * S_W, a.x * S_W) | (qe4x2(a.w * S_W, a.z * S_W) << 16);
    o.y = qe4x2(b.y * S_W, b.x * S_W) | (qe4x2(b.w * S_W, b.z * S_W) << 16);
    reinterpret_cast<uint2*>(q)[i] = o;
}

// ------------------------- rmsnorm (-> e4m3 x S_XN) -------------------------
__global__ void rmsnorm_kernel(const float* __restrict__ x, const float* __restrict__ w)
{
    __shared__ float red[8];
    int token = blockIdx.x;
    int tid = threadIdx.x;  // 256
    float4 v = reinterpret_cast<const float4*>(x + (size_t)token * DM)[tid];
    float ss = v.x * v.x + v.y * v.y + v.z * v.z + v.w * v.w;
#pragma unroll
    for (int o = 16; o; o >>= 1) ss += __shfl_xor_sync(0xffffffffu, ss, o);
    if ((tid & 31) == 0) red[tid >> 5] = ss;
    __syncthreads();
    float tot = 0.f;
#pragma unroll
    for (int i = 0; i < 8; i++) tot += red[i];
    float r = rsqrtf(tot * (1.f / (float)DM) + 1e-6f) * S_XN;
    float4 wv = reinterpret_cast<const float4*>(w)[tid];
    float o0 = v.x * r * wv.x, o1 = v.y * r * wv.y;
    float o2 = v.z * r * wv.z, o3 = v.w * r * wv.w;
    reinterpret_cast<uint32_t*>(g_xn8)[token * 256 + tid] =
        qe4x2(o1, o0) | (qe4x2(o3, o2) << 16);
}

// ------------------------- FP8 GEMM (NT), 4-stage cp.async pipeline -------------------------
// C[M,N] = (A/sa)[M,K] * (B/sb)[N,K]^T via e4m3 mma m16n8k32; desc = 1/(sa*sb).
// MODE 0: split-store (cols<DI: fp32 x_branch; cols>=DI: silu->bf16 g_sg)
// MODE 1: dt epilogue.  MODE 2: residual epilogue.
#define SROWB 48
#define STILEB (128 * SROWB)

template <int MODE>
__global__ void __launch_bounds__(256, 2) gemm_fp8(
    const uint8_t* __restrict__ Aq, const uint8_t* __restrict__ Bq,
    float* __restrict__ Cg, int N, int K, float desc,
    const float* __restrict__ bias, const float* __restrict__ resid,
    const float* __restrict__ scale_ptr)
{
    __shared__ uint8_t sm[4][2][STILEB];   // 48 KB

    const int tid = threadIdx.x, wid = tid >> 5, lane = tid & 31;
    const int bm = blockIdx.y * 128, bn = blockIdx.x * 128;
    const int warp_m = wid >> 2, warp_n = wid & 3;

    float acc[4][4][4];
#pragma unroll
    for (int i = 0; i < 4; i++)
#pragma unroll
        for (int j = 0; j < 4; j++)
#pragma unroll
            for (int q = 0; q < 4; q++) acc[i][j][q] = 0.f;

    const uint8_t* srcs[2] = { Aq + (size_t)bm * K, Bq + (size_t)bn * K };

    const int row = tid >> 1, half = tid & 1;
    const uint32_t smb = cvta_s(sm);
    const uint32_t dst_off = (uint32_t)(row * SROWB + half * 16);

    uint32_t a_off[4], b_off[2];
#pragma unroll
    for (int i = 0; i < 4; i++) {
        int r = warp_m * 64 + i * 16 + (lane & 15);
        a_off[i] = (uint32_t)(r * SROWB + (lane >> 4) * 16);
    }
#pragma unroll
    for (int g = 0; g < 2; g++) {
        int n = warp_n * 32 + g * 16 + ((lane >> 4) & 1) * 8 + (lane & 7);
        b_off[g] = (uint32_t)(n * SROWB + ((lane >> 3) & 1) * 16);
    }

    const int nst = K >> 5;   // 32 fp8 elems per k-step
#pragma unroll
    for (int st = 0; st < 3; st++) {
        uint32_t bufb = smb + (uint32_t)(st * 2 * STILEB);
        const size_t goff = (size_t)row * K + st * 32 + half * 16;
#pragma unroll
        for (int t = 0; t < 2; t++)
            cp_async16(bufb + (uint32_t)(t * STILEB) + dst_off, srcs[t] + goff);
        CP_COMMIT();
    }

    for (int c = 0; c < nst; c++) {
        CP_WAIT(2);
        __syncthreads();
        if (c + 3 < nst) {
            uint32_t bufb = smb + (uint32_t)(((c + 3) & 3) * 2 * STILEB);
            const size_t goff = (size_t)row * K + (c + 3) * 32 + half * 16;
#pragma unroll
            for (int t = 0; t < 2; t++)
                cp_async16(bufb + (uint32_t)(t * STILEB) + dst_off, srcs[t] + goff);
        }
        CP_COMMIT();

        const uint32_t bb = smb + (uint32_t)((c & 3) * 2 * STILEB);
        uint32_t ah[4][4], bh[4][2];
#pragma unroll
        for (int i = 0; i < 4; i++) ldsm4(ah[i], bb + a_off[i]);
#pragma unroll
        for (int g = 0; g < 2; g++) {
            uint32_t r[4];
            ldsm4(r, bb + (uint32_t)STILEB + b_off[g]);
            bh[2 * g][0] = r[0]; bh[2 * g][1] = r[1];
            bh[2 * g + 1][0] = r[2]; bh[2 * g + 1][1] = r[3];
        }
#pragma unroll
        for (int i = 0; i < 4; i++)
#pragma unroll
            for (int j = 0; j < 4; j++) mma_fp8(acc[i][j], ah[i], bh[j]);
    }

    float scale = 0.f;
    if (MODE == 2) scale = 0.5f / (1.f + expf(-scale_ptr[0]));

#pragma unroll
    for (int i = 0; i < 4; i++)
#pragma unroll
        for (int j = 0; j < 4; j++) {
            int rr = bm + warp_m * 64 + i * 16 + (lane >> 2);
            int cc = bn + warp_n * 32 + j * 8 + (lane & 3) * 2;
#pragma unroll
            for (int hrow = 0; hrow < 2; hrow++) {
                size_t r = (size_t)(rr + hrow * 8);
                float v0 = acc[i][j][hrow * 2] * desc;
                float v1 = acc[i][j][hrow * 2 + 1] * desc;
                if (MODE == 0) {
                    if (cc < DI) {
                        *reinterpret_cast<float2*>(g_xbr + r * DI + cc) = make_float2(v0, v1);
                    } else {
                        __nv_bfloat162 hh;
                        hh.x = __float2bfloat16_rn(v0 / (1.f + expf(-v0)));
                        hh.y = __float2bfloat16_rn(v1 / (1.f + expf(-v1)));
                        *reinterpret_cast<__nv_bfloat162*>(g_sg + r * DI + cc - DI) = hh;
                    }
                } else if (MODE == 1) {
                    float p0 = v0 + bias[cc], p1 = v1 + bias[cc + 1];
                    float s0 = fmaxf(p0, 0.f) + log1pf(expf(-fabsf(p0)));
                    float s1 = fmaxf(p1, 0.f) + log1pf(expf(-fabsf(p1)));
                    v0 = tanhf((s0 - 0.0505f) * (0.5f / (0.0495f + 1e-8f))) * 0.099f + 0.0505f;
                    v1 = tanhf((s1 - 0.0505f) * (0.5f / (0.0495f + 1e-8f))) * 0.099f + 0.0505f;
                    *reinterpret_cast<float2*>(Cg + r * N + cc) = make_float2(v0, v1);
                } else {
                    v0 = resid[r * N + cc] + scale * v0;
                    v1 = resid[r * N + cc + 1] + scale * v1;
                    *reinterpret_cast<float2*>(Cg + r * N + cc) = make_float2(v0, v1);
                }
            }
        }
}

// ------------------------- conv4 + SiLU (-> fp32 + e4m3 x S_XC) -------------------------
__global__ void conv_silu_kernel(const float* __restrict__ conv_w, const float* __restrict__ conv_b)
{
    int token = blockIdx.x;
    int t = token & (LSEQ - 1);
    for (int d = threadIdx.x; d < DI; d += blockDim.x) {
        float4 w = *reinterpret_cast<const float4*>(conv_w + (size_t)d * 4);
        float acc = conv_b[d];
        const float* base = g_xbr + (size_t)token * DI + d;
        if (t >= 3) acc = fmaf(w.x, base[-3 * DI], acc);
        if (t >= 2) acc = fmaf(w.y, base[-2 * DI], acc);
        if (t >= 1) acc = fmaf(w.z, base[-1 * DI], acc);
        acc = fmaf(w.w, base[0], acc);
        float s = 1.f / (1.f + expf(-acc));
        float val = acc * s;
        size_t idx = (size_t)token * DI + d;
        g_xc[idx] = val;
        g_xc8[idx] = (uint8_t)(qe4x2(0.f, val * S_XC) & 0xffu);
    }
}

// ------------------------- Bp / Cp projections -------------------------
__global__ void __launch_bounds__(256) bpcp_kernel(const float* __restrict__ W_B,
                                                   const float* __restrict__ W_C)
{
    __shared__ float sx[4][DI];
    int tok0 = blockIdx.x * 4;
    int tid = threadIdx.x;
    for (int i = tid; i < 4 * DI; i += 256) {
        int r = i >> 11, dd = i & (DI - 1);
        sx[r][dd] = g_xc[(size_t)(tok0 + r) * DI + dd];
    }
    __syncthreads();
    int wid = tid >> 5, lane = tid & 31;
#pragma unroll
    for (int oo = 0; oo < 4; oo++) {
        int o = wid + oo * 8;
        const float* Wr = (o < 16) ? (W_B + (size_t)o * DI) : (W_C + (size_t)(o - 16) * DI);
        float a0 = 0.f, a1 = 0.f, a2 = 0.f, a3 = 0.f;
        for (int dd = lane; dd < DI; dd += 32) {
            float w = Wr[dd];
            a0 = fmaf(w, sx[0][dd], a0);
            a1 = fmaf(w, sx[1][dd], a1);
            a2 = fmaf(w, sx[2][dd], a2);
            a3 = fmaf(w, sx[3][dd], a3);
        }
#pragma unroll
        for (int off = 16; off; off >>= 1) {
            a0 += __shfl_xor_sync(0xffffffffu, a0, off);
            a1 += __shfl_xor_sync(0xffffffffu, a1, off);
            a2 += __shfl_xor_sync(0xffffffffu, a2, off);
            a3 += __shfl_xor_sync(0xffffffffu, a3, off);
        }
        if (lane == 0) {
            float* outp = (o < 16) ? g_Bp : g_Cp;
            int oc = (o < 16) ? o : (o - 16);
            outp[(tok0 + 0) * DS + oc] = a0;
            outp[(tok0 + 1) * DS + oc] = a1;
            outp[(tok0 + 2) * DS + oc] = a2;
            outp[(tok0 + 3) * DS + oc] = a3;
        }
    }
}

// ------------------------- selective scan (fused gating + fp8 quantize) -------------------------
template <int CPT>
__global__ void __launch_bounds__(128) scan_kernel(const float* __restrict__ A_log,
                                                   const float* __restrict__ Dp, int cs)
{
    __shared__ __align__(16) float sDT[2][10][128 * CPT];
    __shared__ __align__(16) float sXC[2][10][128 * CPT];
    __shared__ __align__(16) __nv_bfloat16 sSG[2][10][(CPT == 1) ? 128 : 2];
    __shared__ __align__(16) float sB[2][10][16];
    __shared__ __align__(16) float sC[2][10][16];
    __shared__ float warp_part[4];
    __shared__ __align__(8) float slotbuf[2][16];
    __shared__ float s_fac;
    __shared__ __align__(8) ull mbar;

    const int tid = threadIdx.x;
    const int lane = tid & 31, wid = tid >> 5;
    uint32_t rank; asm("mov.u32 %0, %%cluster_ctarank;" : "=r"(rank));
    const int b = blockIdx.x / cs;
    const int d0 = (int)rank * 128 * CPT;

    const uint32_t mbar_u32 = cvta_s(&mbar);
    const uint32_t slot_u32 = cvta_s(slotbuf);
    if (tid == 0) MBAR_INIT(mbar_u32, (uint32_t)cs);
    asm volatile("barrier.cluster.arrive.aligned;" ::: "memory");
    asm volatile("barrier.cluster.wait.aligned;" ::: "memory");

    ull ALn[CPT][2], ALe[CPT][6], h2[CPT][8];
    float Dv[CPT];
#pragma unroll
    for (int j = 0; j < CPT; j++) {
        int d = d0 + j * 128 + tid;
#pragma unroll
        for (int p = 0; p < 8; p++) {
            float a0 = A_log[(size_t)d * 16 + 2 * p];
            float a1 = A_log[(size_t)d * 16 + 2 * p + 1];
            float A0 = -expf(10.f * tanhf(0.1f * a0));
            float A1 = -expf(10.f * tanhf(0.1f * a1));
            if (p < 2) ALn[j][p] = pk2(A0, A1);
            else       ALe[j][p - 2] = pk2(A0 * 1.44269504f, A1 * 1.44269504f);
            h2[j][p] = pk2(0.f, 0.f);
        }
        Dv[j] = Dp[d];
    }
    const float* dt_base = g_dt + (size_t)b * LSEQ * DI + d0;
    const float* xc_base = g_xc + (size_t)b * LSEQ * DI + d0;
    const __nv_bfloat16* sg_base = g_sg + (size_t)b * LSEQ * DI + d0;
    uint8_t* g8_base = g_g8 + (size_t)b * LSEQ * DI + d0;
    const float* Bp_base = g_Bp + (size_t)b * LSEQ * DS;
    const float* Cp_base = g_Cp + (size_t)b * LSEQ * DS;

    const uint32_t sdt_a = cvta_s(sDT), sxc_a = cvta_s(sXC), ssg_a = cvta_s(sSG);
    const uint32_t sb_a = cvta_s(sB), sc_a = cvta_s(sC);
    const int R16 = 32 * CPT;

    auto stage = [&](int cidx) {
        int buf = cidx & 1;
        int rows = (cidx == 102) ? 4 : 10;
        int t0 = cidx * 10;
        for (int i = tid; i < rows * R16; i += 128) {
            int s = i / R16, u = i % R16;
            cp_async16(sdt_a + (uint32_t)((buf * 10 + s) * R16 + u) * 16,
                       dt_base + (size_t)(t0 + s) * DI + u * 4);
            cp_async16(sxc_a + (uint32_t)((buf * 10 + s) * R16 + u) * 16,
                       xc_base + (size_t)(t0 + s) * DI + u * 4);
        }
        if (CPT == 1) {
            for (int i = tid; i < rows * 16; i += 128) {
                int s = i >> 4, u = i & 15;
                cp_async16(ssg_a + (uint32_t)((buf * 10 + s) * 128 + u * 8) * 2,
                           sg_base + (size_t)(t0 + s) * DI + u * 8);
            }
        }
        for (int i = tid; i < rows * 4; i += 128) {
            int s = i >> 2, u = i & 3;
            cp_async16(sb_a + (uint32_t)((buf * 10 + s) * 4 + u) * 16,
                       Bp_base + (size_t)(t0 + s) * DS + u * 4);
            cp_async16(sc_a + (uint32_t)((buf * 10 + s) * 4 + u) * 16,
                       Cp_base + (size_t)(t0 + s) * DS + u * 4);
        }
        CP_COMMIT();
    };

    const ull k24 = pk2(1.f / 24.f, 1.f / 24.f);
    const ull k6  = pk2(1.f / 6.f,  1.f / 6.f);
    const ull kh  = pk2(0.5f, 0.5f);
    const ull k1  = pk2(1.f, 1.f);

    stage(0);

    auto chunk_body = [&](int c, auto NSc) {
        constexpr int NS = decltype(NSc)::value;
        const int bc = c & 1;
        const int t0 = c * 10;
        float dtv[CPT][NS], xcv[CPT][NS], sgv[CPT][NS];
#pragma unroll
        for (int j = 0; j < CPT; j++)
#pragma unroll
            for (int s = 0; s < NS; s++) {
                dtv[j][s] = sDT[bc][s][j * 128 + tid];
                xcv[j][s] = sXC[bc][s][j * 128 + tid];
                if (CPT == 1)
                    sgv[j][s] = __bfloat162float(sSG[bc][s][tid]);
                else
                    sgv[j][s] = __bfloat162float(sg_base[(size_t)(t0 + s) * DI + j * 128 + tid]);
            }

#pragma unroll
        for (int s = 0; s < NS; s++) {
            const ull* B2 = reinterpret_cast<const ull*>(sB[bc][s]);
            const ull* C2 = reinterpret_cast<const ull*>(sC[bc][s]);
#pragma unroll
            for (int j = 0; j < CPT; j++) {
                float dt_ = dtv[j][s], xc_ = xcv[j][s];
                float dtx = dt_ * xc_;
                ull dt2 = pk2(dt_, dt_), dtx2 = pk2(dtx, dtx);
#pragma unroll
                for (int p = 0; p < 2; p++) {
                    ull w = mul2_(dt2, ALn[j][p]);
                    ull e = fma2_(w, k24, k6);
                    e = fma2_(e, w, kh);
                    e = fma2_(e, w, k1);
                    e = fma2_(e, w, k1);
                    h2[j][p] = fma2_(h2[j][p], e, mul2_(B2[p], dtx2));
                }
#pragma unroll
                for (int p = 2; p < 8; p++) {
                    float2 ww = upk2(mul2_(dt2, ALe[j][p - 2]));
                    ull dA = pk2(ex2_(ww.x), ex2_(ww.y));
                    h2[j][p] = fma2_(h2[j][p], dA, mul2_(B2[p], dtx2));
                }
            }
            if (s == 0) {  // norm event (t0 % 10 == 0 always)
                ull ss2 = pk2(0.f, 0.f);
#pragma unroll
                for (int j = 0; j < CPT; j++)
#pragma unroll
                    for (int p = 0; p < 8; p++) ss2 = fma2_(h2[j][p], h2[j][p], ss2);
                float2 sp = upk2(ss2);
                float ss = sp.x + sp.y;
#pragma unroll
                for (int o = 16; o; o >>= 1) ss += __shfl_xor_sync(0xffffffffu, ss, o);
                if (lane == 0) warp_part[wid] = ss;
                __syncthreads();
                int par = c & 1;
                if (wid == 0) {
                    float v = warp_part[lane & 3];
                    v += __shfl_xor_sync(0xffffffffu, v, 1);
                    v += __shfl_xor_sync(0xffffffffu, v, 2);
                    if (lane < cs) {
                        uint32_t myslot = slot_u32 + (uint32_t)((par * 16 + (int)rank) * 4);
                        ST_REMOTE_F32(myslot, (uint32_t)lane, v);
                        MBAR_ARRIVE_REMOTE(mbar_u32, (uint32_t)lane);
                    }
                    MBAR_WAIT_CLU(mbar_u32, (uint32_t)(c & 1));
                    float w = (lane < cs) ? slotbuf[par][lane] : 0.f;
                    w += __shfl_xor_sync(0xffffffffu, w, 8);
                    w += __shfl_xor_sync(0xffffffffu, w, 4);
                    w += __shfl_xor_sync(0xffffffffu, w, 2);
                    w += __shfl_xor_sync(0xffffffffu, w, 1);
                    if (lane == 0) s_fac = fminf(20.f / (sqrtf(w) + 1e-8f), 1.f);
                }
                __syncthreads();
                float fac = s_fac;
                ull fac2 = pk2(fac, fac);
#pragma unroll
                for (int j = 0; j < CPT; j++)
#pragma unroll
                    for (int p = 0; p < 8; p++) h2[j][p] = mul2_(h2[j][p], fac2);
            }
#pragma unroll
            for (int j = 0; j < CPT; j++) {
                ull y2 = pk2(Dv[j] * xcv[j][s], 0.f);
#pragma unroll
                for (int p = 0; p < 8; p++) y2 = fma2_(h2[j][p], C2[p], y2);
                float2 yy = upk2(y2);
                float gated = (yy.x + yy.y) * sgv[j][s] * S_G;
                g8_base[(size_t)(t0 + s) * DI + j * 128 + tid] =
                    (uint8_t)(qe4x2(0.f, gated) & 0xffu);
            }
        }
    };

    for (int c = 0; c <= 102; c++) {
        if (c < 102) { stage(c + 1); CP_WAIT(1); }
        else         { CP_WAIT(0); }
        __syncthreads();
        if (c < 102) chunk_body(c, std::integral_constant<int, 10>{});
        else         chunk_body(c, std::integral_constant<int, 4>{});
    }
}

// ------------------------- launch -------------------------
extern "C" void kernel_launch(void* const* d_in, const int* in_sizes, int n_in,
                              void* d_out, int out_size)
{
    const float* x       = (const float*)d_in[0];
    const float* norm_w  = (const float*)d_in[1];
    const float* W_in    = (const float*)d_in[2];
    const float* conv_w  = (const float*)d_in[3];
    const float* conv_b  = (const float*)d_in[4];
    const float* W_dt    = (const float*)d_in[5];
    const float* b_dt    = (const float*)d_in[6];
    const float* W_B     = (const float*)d_in[7];
    const float* W_C     = (const float*)d_in[8];
    const float* A_log   = (const float*)d_in[9];
    const float* D_param = (const float*)d_in[10];
    const float* W_out   = (const float*)d_in[11];
    const float* r_scale = (const float*)d_in[12];
    float* out = (float*)d_out;

    void *p_dt, *p_xn8, *p_xc8, *p_g8, *p_wi8, *p_wd8, *p_wo8;
    cudaGetSymbolAddress(&p_dt, g_dt);
    cudaGetSymbolAddress(&p_xn8, g_xn8);
    cudaGetSymbolAddress(&p_xc8, g_xc8);
    cudaGetSymbolAddress(&p_g8, g_g8);
    cudaGetSymbolAddress(&p_wi8, g_Win8);
    cudaGetSymbolAddress(&p_wd8, g_Wdt8);
    cudaGetSymbolAddress(&p_wo8, g_Wout8);

    static cudaStream_t sA = nullptr, sB2 = nullptr;
    static cudaEvent_t ev[6] = {};
    if (!sA) {
        cudaStreamCreateWithFlags(&sA, cudaStreamNonBlocking);
        cudaStreamCreateWithFlags(&sB2, cudaStreamNonBlocking);
        for (int i = 0; i < 6; i++) cudaEventCreateWithFlags(&ev[i], cudaEventDisableTiming);
    }

    // fork sA for weight conversions
    cudaEventRecord(ev[0], 0);
    cudaStreamWaitEvent(sA, ev[0], 0);
    cvt_w8_kernel<<<(2 * DI * DM / 8) / 256, 256, 0, sA>>>(W_in, (uint8_t*)p_wi8, 2 * DI * DM / 8);
    cudaEventRecord(ev[1], sA);
    cvt_w8_kernel<<<(DI * DI / 8) / 256, 256, 0, sA>>>(W_dt, (uint8_t*)p_wd8, DI * DI / 8);
    cudaEventRecord(ev[2], sA);
    cvt_w8_kernel<<<(DM * DI / 8) / 256, 256, 0, sA>>>(W_out, (uint8_t*)p_wo8, DM * DI / 8);
    cudaEventRecord(ev[3], sA);

    // main stream
    rmsnorm_kernel<<<NTOK, 256>>>(x, norm_w);
    cudaStreamWaitEvent(0, ev[1], 0);
    gemm_fp8<0><<<dim3(4096 / 128, NTOK / 128), 256>>>(
        (const uint8_t*)p_xn8, (const uint8_t*)p_wi8,
        nullptr, 4096, 1024, DESC0, nullptr, nullptr, nullptr);
    conv_silu_kernel<<<NTOK, 256>>>(conv_w, conv_b);

    // fork bpcp in parallel with dt GEMM
    cudaEventRecord(ev[4], 0);
    cudaStreamWaitEvent(sB2, ev[4], 0);
    bpcp_kernel<<<NTOK / 4, 256, 0, sB2>>>(W_B, W_C);
    cudaEventRecord(ev[5], sB2);

    cudaStreamWaitEvent(0, ev[2], 0);
    gemm_fp8<1><<<dim3(DI / 128, NTOK / 128), 256>>>(
        (const uint8_t*)p_xc8, (const uint8_t*)p_wd8,
        (float*)p_dt, DI, DI, DESC1, b_dt, nullptr, nullptr);
    cudaStreamWaitEvent(0, ev[5], 0);

    // selective scan: cluster-16 (CPT=1) with cluster-8 (CPT=2) fallback
    {
        cudaError_t e = cudaFuncSetAttribute(
            (const void*)scan_kernel<1>,
            cudaFuncAttributeNonPortableClusterSizeAllowed, 1);
        cudaLaunchConfig_t cfg = {};
        cudaLaunchAttribute at[1];
        at[0].id = cudaLaunchAttributeClusterDimension;
        cfg.attrs = at;
        cfg.numAttrs = 1;
        cfg.blockDim = dim3(128, 1, 1);
        cfg.stream = 0;
        if (e == cudaSuccess) {
            int cs = 16;
            at[0].val.clusterDim = {16, 1, 1};
            cfg.gridDim = dim3(32, 1, 1);
            cudaLaunchKernelEx(&cfg, scan_kernel<1>, A_log, D_param, cs);
        } else {
            (void)cudaGetLastError();
            int cs = 8;
            at[0].val.clusterDim = {8, 1, 1};
            cfg.gridDim = dim3(16, 1, 1);
            cudaLaunchKernelEx(&cfg, scan_kernel<2>, A_log, D_param, cs);
        }
    }

    cudaStreamWaitEvent(0, ev[3], 0);
    gemm_fp8<2><<<dim3(DM / 128, NTOK / 128), 256>>>(
        (const uint8_t*)p_g8, (const uint8_t*)p_wo8,
        out, DM, DI, DESC2, nullptr, x, r_scale);
}

// round 15
// speedup vs baseline: 1.0014x; 1.0014x over previous
#include <cuda_runtime.h>
#include <cuda_bf16.h>
#include <cstdint>
#include <cstddef>
#include <type_traits>

#define NTOK 2048
#define DM   1024
#define DI   2048
#define DS   16
#define LSEQ 1024

// per-tensor fp8 scales (power of 2)
#define S_XN   32.f
#define S_W    1024.f
#define S_XC   1024.f
#define S_G    4096.f
#define DESC0  (1.f / (S_XN * S_W))
#define DESC1  (1.f / (S_XC * S_W))
#define DESC2  (1.f / (S_G * S_W))

typedef unsigned long long ull;

// ------------------------- scratch -------------------------
__device__ float g_xbr[NTOK * DI];                 // x_branch fp32 (conv input)
__device__ __nv_bfloat16 g_sg[NTOK * DI];          // silu(gate) bf16
__device__ float g_xc[NTOK * DI];                  // conv+silu fp32
__device__ float g_dt[NTOK * DI];
__device__ float g_Bp[NTOK * DS];
__device__ float g_Cp[NTOK * DS];

__device__ uint8_t g_xn8[NTOK * DM];               // e4m3 operands
__device__ uint8_t g_xc8[NTOK * DI];
__device__ uint8_t g_g8[NTOK * DI];
__device__ uint8_t g_Win8[2 * DI * DM];
__device__ uint8_t g_Wdt8[DI * DI];
__device__ uint8_t g_Wout8[DM * DI];

// ------------------------- PTX helpers -------------------------
__device__ __forceinline__ uint32_t cvta_s(const void* p) {
    uint32_t a;
    asm("{.reg .u64 t; cvta.to.shared.u64 t, %1; cvt.u32.u64 %0, t;}" : "=r"(a) : "l"(p));
    return a;
}
__device__ __forceinline__ void cp_async16(uint32_t saddr, const void* gaddr) {
    asm volatile("cp.async.cg.shared.global [%0], [%1], 16;" :: "r"(saddr), "l"(gaddr));
}
#define CP_COMMIT() asm volatile("cp.async.commit_group;" ::: "memory")
#define CP_WAIT(n)  asm volatile("cp.async.wait_group %0;" :: "n"(n) : "memory")

__device__ __forceinline__ void ldsm4(uint32_t* r, uint32_t addr) {
    asm volatile("ldmatrix.sync.aligned.m8n8.x4.shared.b16 {%0,%1,%2,%3}, [%4];"
                 : "=r"(r[0]), "=r"(r[1]), "=r"(r[2]), "=r"(r[3]) : "r"(addr));
}
__device__ __forceinline__ void mma_fp8(float* c, const uint32_t* a, const uint32_t* b) {
    asm volatile("mma.sync.aligned.m16n8k32.row.col.f32.e4m3.e4m3.f32 "
                 "{%0,%1,%2,%3},{%4,%5,%6,%7},{%8,%9},{%0,%1,%2,%3};"
                 : "+f"(c[0]), "+f"(c[1]), "+f"(c[2]), "+f"(c[3])
                 : "r"(a[0]), "r"(a[1]), "r"(a[2]), "r"(a[3]), "r"(b[0]), "r"(b[1]));
}
// byte0 = lo, byte1 = hi
__device__ __forceinline__ uint32_t qe4x2(float hi, float lo) {
    uint16_t r;
    asm("cvt.rn.satfinite.e4m3x2.f32 %0, %1, %2;" : "=h"(r) : "f"(hi), "f"(lo));
    return (uint32_t)r;
}

__device__ __forceinline__ ull pk2(float lo, float hi) {
    ull r; asm("mov.b64 %0,{%1,%2};" : "=l"(r) : "f"(lo), "f"(hi)); return r;
}
__device__ __forceinline__ float2 upk2(ull v) {
    float2 f; asm("mov.b64 {%0,%1},%2;" : "=f"(f.x), "=f"(f.y) : "l"(v)); return f;
}
__device__ __forceinline__ ull fma2_(ull a, ull b, ull c) {
    ull d; asm("fma.rn.f32x2 %0,%1,%2,%3;" : "=l"(d) : "l"(a), "l"(b), "l"(c)); return d;
}
__device__ __forceinline__ ull mul2_(ull a, ull b) {
    ull d; asm("mul.rn.f32x2 %0,%1,%2;" : "=l"(d) : "l"(a), "l"(b)); return d;
}
__device__ __forceinline__ float ex2_(float x) {
    float y; asm("ex2.approx.f32 %0,%1;" : "=f"(y) : "f"(x)); return y;
}

#define MBAR_INIT(addr, cnt) \
    asm volatile("mbarrier.init.shared.b64 [%0], %1;" :: "r"(addr), "r"(cnt) : "memory")

#define MBAR_WAIT_CLU(addr, par) do {                                               \
    uint32_t _m = (addr); uint32_t _p = (par); uint32_t _d;                         \
    asm volatile("{\n\t.reg .pred p;\n\t"                                           \
        "mbarrier.try_wait.parity.acquire.cluster.shared::cta.b64 p, [%1], %2;\n\t" \
        "selp.b32 %0,1,0,p;\n\t}" : "=r"(_d) : "r"(_m), "r"(_p) : "memory");        \
    if (!_d) {                                                                      \
        asm volatile("{\n\t.reg .pred P1;\n\t"                                      \
        "WLC_%=:\n\t"                                                               \
        "mbarrier.try_wait.parity.acquire.cluster.shared::cta.b64 P1, [%0], %1, 0x989680;\n\t" \
        "@P1 bra.uni WDC_%=;\n\t"                                                   \
        "bra.uni WLC_%=;\n\t"                                                       \
        "WDC_%=:\n\t}" :: "r"(_m), "r"(_p) : "memory");                             \
    } } while (0)

#define ST_REMOTE_F32(laddr, rnk, val) \
    asm volatile("{.reg .b32 ra; mapa.shared::cluster.u32 ra, %0, %1;" \
                 " st.shared::cluster.f32 [ra], %2;}" \
                 :: "r"(laddr), "r"(rnk), "f"(val) : "memory")

#define MBAR_ARRIVE_REMOTE(laddr, rnk) \
    asm volatile("{.reg .b32 ra; mapa.shared::cluster.u32 ra, %0, %1;" \
                 " mbarrier.arrive.shared::cluster.b64 _, [ra];}" \
                 :: "r"(laddr), "r"(rnk) : "memory")

// ------------------------- fp32 -> e4m3 weight conversion (x S_W) -------------------------
__global__ void cvt_w8_kernel(const float* __restrict__ src, uint8_t* __restrict__ q, int n8)
{
    int i = blockIdx.x * blockDim.x + threadIdx.x;
    if (i >= n8) return;
    float4 a = reinterpret_cast<const float4*>(src)[2 * i];
    float4 b = reinterpret_cast<const float4*>(src)[2 * i + 1];
    uint2 o;
    o.x = qe4x2(a.y * S_W, a.x * S_W) | (qe4x2(a.w * S_W, a.z * S_W) << 16);
    o.y = qe4x2(b.y * S_W, b.x * S_W) | (qe4x2(b.w * S_W, b.z * S_W) << 16);
    reinterpret_cast<uint2*>(q)[i] = o;
}

// ------------------------- rmsnorm (-> e4m3 x S_XN) -------------------------
__global__ void rmsnorm_kernel(const float* __restrict__ x, const float* __restrict__ w)
{
    __shared__ float red[8];
    int token = blockIdx.x;
    int tid = threadIdx.x;  // 256
    float4 v = reinterpret_cast<const float4*>(x + (size_t)token * DM)[tid];
    float ss = v.x * v.x + v.y * v.y + v.z * v.z + v.w * v.w;
#pragma unroll
    for (int o = 16; o; o >>= 1) ss += __shfl_xor_sync(0xffffffffu, ss, o);
    if ((tid & 31) == 0) red[tid >> 5] = ss;
    __syncthreads();
    float tot = 0.f;
#pragma unroll
    for (int i = 0; i < 8; i++) tot += red[i];
    float r = rsqrtf(tot * (1.f / (float)DM) + 1e-6f) * S_XN;
    float4 wv = reinterpret_cast<const float4*>(w)[tid];
    float o0 = v.x * r * wv.x, o1 = v.y * r * wv.y;
    float o2 = v.z * r * wv.z, o3 = v.w * r * wv.w;
    reinterpret_cast<uint32_t*>(g_xn8)[token * 256 + tid] =
        qe4x2(o1, o0) | (qe4x2(o3, o2) << 16);
}

// ------------------------- FP8 GEMM (NT), 4-stage cp.async pipeline -------------------------
// C[M,N] = (A/sa)[M,K] * (B/sb)[N,K]^T via e4m3 mma m16n8k32; desc = 1/(sa*sb).
// MODE 0: split-store (cols<DI: fp32 x_branch; cols>=DI: silu->bf16 g_sg)
// MODE 1: dt epilogue.  MODE 2: residual epilogue.
#define SROWB 48
#define STILEB (128 * SROWB)

template <int MODE>
__global__ void __launch_bounds__(256, 2) gemm_fp8(
    const uint8_t* __restrict__ Aq, const uint8_t* __restrict__ Bq,
    float* __restrict__ Cg, int N, int K, float desc,
    const float* __restrict__ bias, const float* __restrict__ resid,
    const float* __restrict__ scale_ptr)
{
    __shared__ uint8_t sm[4][2][STILEB];   // 48 KB

    const int tid = threadIdx.x, wid = tid >> 5, lane = tid & 31;
    const int bm = blockIdx.y * 128, bn = blockIdx.x * 128;
    const int warp_m = wid >> 2, warp_n = wid & 3;

    float acc[4][4][4];
#pragma unroll
    for (int i = 0; i < 4; i++)
#pragma unroll
        for (int j = 0; j < 4; j++)
#pragma unroll
            for (int q = 0; q < 4; q++) acc[i][j][q] = 0.f;

    const uint8_t* srcs[2] = { Aq + (size_t)bm * K, Bq + (size_t)bn * K };

    const int row = tid >> 1, half = tid & 1;
    const uint32_t smb = cvta_s(sm);
    const uint32_t dst_off = (uint32_t)(row * SROWB + half * 16);

    uint32_t a_off[4], b_off[2];
#pragma unroll
    for (int i = 0; i < 4; i++) {
        int r = warp_m * 64 + i * 16 + (lane & 15);
        a_off[i] = (uint32_t)(r * SROWB + (lane >> 4) * 16);
    }
#pragma unroll
    for (int g = 0; g < 2; g++) {
        int n = warp_n * 32 + g * 16 + ((lane >> 4) & 1) * 8 + (lane & 7);
        b_off[g] = (uint32_t)(n * SROWB + ((lane >> 3) & 1) * 16);
    }

    const int nst = K >> 5;   // 32 fp8 elems per k-step
#pragma unroll
    for (int st = 0; st < 3; st++) {
        uint32_t bufb = smb + (uint32_t)(st * 2 * STILEB);
        const size_t goff = (size_t)row * K + st * 32 + half * 16;
#pragma unroll
        for (int t = 0; t < 2; t++)
            cp_async16(bufb + (uint32_t)(t * STILEB) + dst_off, srcs[t] + goff);
        CP_COMMIT();
    }

    for (int c = 0; c < nst; c++) {
        CP_WAIT(2);
        __syncthreads();
        if (c + 3 < nst) {
            uint32_t bufb = smb + (uint32_t)(((c + 3) & 3) * 2 * STILEB);
            const size_t goff = (size_t)row * K + (c + 3) * 32 + half * 16;
#pragma unroll
            for (int t = 0; t < 2; t++)
                cp_async16(bufb + (uint32_t)(t * STILEB) + dst_off, srcs[t] + goff);
        }
        CP_COMMIT();

        const uint32_t bb = smb + (uint32_t)((c & 3) * 2 * STILEB);
        uint32_t ah[4][4], bh[4][2];
#pragma unroll
        for (int i = 0; i < 4; i++) ldsm4(ah[i], bb + a_off[i]);
#pragma unroll
        for (int g = 0; g < 2; g++) {
            uint32_t r[4];
            ldsm4(r, bb + (uint32_t)STILEB + b_off[g]);
            bh[2 * g][0] = r[0]; bh[2 * g][1] = r[1];
            bh[2 * g + 1][0] = r[2]; bh[2 * g + 1][1] = r[3];
        }
#pragma unroll
        for (int i = 0; i < 4; i++)
#pragma unroll
            for (int j = 0; j < 4; j++) mma_fp8(acc[i][j], ah[i], bh[j]);
    }

    float scale = 0.f;
    if (MODE == 2) scale = 0.5f / (1.f + expf(-scale_ptr[0]));

#pragma unroll
    for (int i = 0; i < 4; i++)
#pragma unroll
        for (int j = 0; j < 4; j++) {
            int rr = bm + warp_m * 64 + i * 16 + (lane >> 2);
            int cc = bn + warp_n * 32 + j * 8 + (lane & 3) * 2;
#pragma unroll
            for (int hrow = 0; hrow < 2; hrow++) {
                size_t r = (size_t)(rr + hrow * 8);
                float v0 = acc[i][j][hrow * 2] * desc;
                float v1 = acc[i][j][hrow * 2 + 1] * desc;
                if (MODE == 0) {
                    if (cc < DI) {
                        *reinterpret_cast<float2*>(g_xbr + r * DI + cc) = make_float2(v0, v1);
                    } else {
                        __nv_bfloat162 hh;
                        hh.x = __float2bfloat16_rn(v0 / (1.f + expf(-v0)));
                        hh.y = __float2bfloat16_rn(v1 / (1.f + expf(-v1)));
                        *reinterpret_cast<__nv_bfloat162*>(g_sg + r * DI + cc - DI) = hh;
                    }
                } else if (MODE == 1) {
                    float p0 = v0 + bias[cc], p1 = v1 + bias[cc + 1];
                    float s0 = fmaxf(p0, 0.f) + log1pf(expf(-fabsf(p0)));
                    float s1 = fmaxf(p1, 0.f) + log1pf(expf(-fabsf(p1)));
                    v0 = tanhf((s0 - 0.0505f) * (0.5f / (0.0495f + 1e-8f))) * 0.099f + 0.0505f;
                    v1 = tanhf((s1 - 0.0505f) * (0.5f / (0.0495f + 1e-8f))) * 0.099f + 0.0505f;
                    *reinterpret_cast<float2*>(Cg + r * N + cc) = make_float2(v0, v1);
                } else {
                    v0 = resid[r * N + cc] + scale * v0;
                    v1 = resid[r * N + cc + 1] + scale * v1;
                    *reinterpret_cast<float2*>(Cg + r * N + cc) = make_float2(v0, v1);
                }
            }
        }
}

// ------------------------- conv4 + SiLU (-> fp32 + e4m3 x S_XC) -------------------------
__global__ void conv_silu_kernel(const float* __restrict__ conv_w, const float* __restrict__ conv_b)
{
    int token = blockIdx.x;
    int t = token & (LSEQ - 1);
    for (int d = threadIdx.x; d < DI; d += blockDim.x) {
        float4 w = *reinterpret_cast<const float4*>(conv_w + (size_t)d * 4);
        float acc = conv_b[d];
        const float* base = g_xbr + (size_t)token * DI + d;
        if (t >= 3) acc = fmaf(w.x, base[-3 * DI], acc);
        if (t >= 2) acc = fmaf(w.y, base[-2 * DI], acc);
        if (t >= 1) acc = fmaf(w.z, base[-1 * DI], acc);
        acc = fmaf(w.w, base[0], acc);
        float s = 1.f / (1.f + expf(-acc));
        float val = acc * s;
        size_t idx = (size_t)token * DI + d;
        g_xc[idx] = val;
        g_xc8[idx] = (uint8_t)(qe4x2(0.f, val * S_XC) & 0xffu);
    }
}

// ------------------------- Bp / Cp projections -------------------------
__global__ void __launch_bounds__(256) bpcp_kernel(const float* __restrict__ W_B,
                                                   const float* __restrict__ W_C)
{
    __shared__ float sx[4][DI];
    int tok0 = blockIdx.x * 4;
    int tid = threadIdx.x;
    for (int i = tid; i < 4 * DI; i += 256) {
        int r = i >> 11, dd = i & (DI - 1);
        sx[r][dd] = g_xc[(size_t)(tok0 + r) * DI + dd];
    }
    __syncthreads();
    int wid = tid >> 5, lane = tid & 31;
#pragma unroll
    for (int oo = 0; oo < 4; oo++) {
        int o = wid + oo * 8;
        const float* Wr = (o < 16) ? (W_B + (size_t)o * DI) : (W_C + (size_t)(o - 16) * DI);
        float a0 = 0.f, a1 = 0.f, a2 = 0.f, a3 = 0.f;
        for (int dd = lane; dd < DI; dd += 32) {
            float w = Wr[dd];
            a0 = fmaf(w, sx[0][dd], a0);
            a1 = fmaf(w, sx[1][dd], a1);
            a2 = fmaf(w, sx[2][dd], a2);
            a3 = fmaf(w, sx[3][dd], a3);
        }
#pragma unroll
        for (int off = 16; off; off >>= 1) {
            a0 += __shfl_xor_sync(0xffffffffu, a0, off);
            a1 += __shfl_xor_sync(0xffffffffu, a1, off);
            a2 += __shfl_xor_sync(0xffffffffu, a2, off);
            a3 += __shfl_xor_sync(0xffffffffu, a3, off);
        }
        if (lane == 0) {
            float* outp = (o < 16) ? g_Bp : g_Cp;
            int oc = (o < 16) ? o : (o - 16);
            outp[(tok0 + 0) * DS + oc] = a0;
            outp[(tok0 + 1) * DS + oc] = a1;
            outp[(tok0 + 2) * DS + oc] = a2;
            outp[(tok0 + 3) * DS + oc] = a3;
        }
    }
}

// ------------------------- selective scan (fused gating + fp8 quantize) -------------------------
template <int CPT>
__global__ void __launch_bounds__(128) scan_kernel(const float* __restrict__ A_log,
                                                   const float* __restrict__ Dp, int cs)
{
    __shared__ __align__(16) float sDT[2][10][128 * CPT];
    __shared__ __align__(16) float sXC[2][10][128 * CPT];
    __shared__ __align__(16) __nv_bfloat16 sSG[2][10][(CPT == 1) ? 128 : 2];
    __shared__ __align__(16) float sB[2][10][16];
    __shared__ __align__(16) float sC[2][10][16];
    __shared__ float warp_part[4];
    __shared__ __align__(8) float slotbuf[2][16];
    __shared__ float s_fac;
    __shared__ __align__(8) ull mbar;

    const int tid = threadIdx.x;
    const int lane = tid & 31, wid = tid >> 5;
    uint32_t rank; asm("mov.u32 %0, %%cluster_ctarank;" : "=r"(rank));
    const int b = blockIdx.x / cs;
    const int d0 = (int)rank * 128 * CPT;

    const uint32_t mbar_u32 = cvta_s(&mbar);
    const uint32_t slot_u32 = cvta_s(slotbuf);
    if (tid == 0) MBAR_INIT(mbar_u32, (uint32_t)cs);
    asm volatile("barrier.cluster.arrive.aligned;" ::: "memory");
    asm volatile("barrier.cluster.wait.aligned;" ::: "memory");

    ull ALn[CPT][2], ALe[CPT][6], h2[CPT][8];
    float Dv[CPT];
#pragma unroll
    for (int j = 0; j < CPT; j++) {
        int d = d0 + j * 128 + tid;
#pragma unroll
        for (int p = 0; p < 8; p++) {
            float a0 = A_log[(size_t)d * 16 + 2 * p];
            float a1 = A_log[(size_t)d * 16 + 2 * p + 1];
            float A0 = -expf(10.f * tanhf(0.1f * a0));
            float A1 = -expf(10.f * tanhf(0.1f * a1));
            if (p < 2) ALn[j][p] = pk2(A0, A1);
            else       ALe[j][p - 2] = pk2(A0 * 1.44269504f, A1 * 1.44269504f);
            h2[j][p] = pk2(0.f, 0.f);
        }
        Dv[j] = Dp[d];
    }
    const float* dt_base = g_dt + (size_t)b * LSEQ * DI + d0;
    const float* xc_base = g_xc + (size_t)b * LSEQ * DI + d0;
    const __nv_bfloat16* sg_base = g_sg + (size_t)b * LSEQ * DI + d0;
    uint8_t* g8_base = g_g8 + (size_t)b * LSEQ * DI + d0;
    const float* Bp_base = g_Bp + (size_t)b * LSEQ * DS;
    const float* Cp_base = g_Cp + (size_t)b * LSEQ * DS;

    const uint32_t sdt_a = cvta_s(sDT), sxc_a = cvta_s(sXC), ssg_a = cvta_s(sSG);
    const uint32_t sb_a = cvta_s(sB), sc_a = cvta_s(sC);
    const int R16 = 32 * CPT;

    auto stage = [&](int cidx) {
        int buf = cidx & 1;
        int rows = (cidx == 102) ? 4 : 10;
        int t0 = cidx * 10;
        for (int i = tid; i < rows * R16; i += 128) {
            int s = i / R16, u = i % R16;
            cp_async16(sdt_a + (uint32_t)((buf * 10 + s) * R16 + u) * 16,
                       dt_base + (size_t)(t0 + s) * DI + u * 4);
            cp_async16(sxc_a + (uint32_t)((buf * 10 + s) * R16 + u) * 16,
                       xc_base + (size_t)(t0 + s) * DI + u * 4);
        }
        if (CPT == 1) {
            for (int i = tid; i < rows * 16; i += 128) {
                int s = i >> 4, u = i & 15;
                cp_async16(ssg_a + (uint32_t)((buf * 10 + s) * 128 + u * 8) * 2,
                           sg_base + (size_t)(t0 + s) * DI + u * 8);
            }
        }
        for (int i = tid; i < rows * 4; i += 128) {
            int s = i >> 2, u = i & 3;
            cp_async16(sb_a + (uint32_t)((buf * 10 + s) * 4 + u) * 16,
                       Bp_base + (size_t)(t0 + s) * DS + u * 4);
            cp_async16(sc_a + (uint32_t)((buf * 10 + s) * 4 + u) * 16,
                       Cp_base + (size_t)(t0 + s) * DS + u * 4);
        }
        CP_COMMIT();
    };

    const ull k24 = pk2(1.f / 24.f, 1.f / 24.f);
    const ull k6  = pk2(1.f / 6.f,  1.f / 6.f);
    const ull kh  = pk2(0.5f, 0.5f);
    const ull k1  = pk2(1.f, 1.f);

    stage(0);

    auto chunk_body = [&](int c, auto NSc) {
        constexpr int NS = decltype(NSc)::value;
        const int bc = c & 1;
        const int t0 = c * 10;
        float dtv[CPT][NS], xcv[CPT][NS], sgv[CPT][NS];
#pragma unroll
        for (int j = 0; j < CPT; j++)
#pragma unroll
            for (int s = 0; s < NS; s++) {
                dtv[j][s] = sDT[bc][s][j * 128 + tid];
                xcv[j][s] = sXC[bc][s][j * 128 + tid];
                if (CPT == 1)
                    sgv[j][s] = __bfloat162float(sSG[bc][s][tid]);
                else
                    sgv[j][s] = __bfloat162float(sg_base[(size_t)(t0 + s) * DI + j * 128 + tid]);
            }

#pragma unroll
        for (int s = 0; s < NS; s++) {
            const ull* B2 = reinterpret_cast<const ull*>(sB[bc][s]);
            const ull* C2 = reinterpret_cast<const ull*>(sC[bc][s]);
#pragma unroll
            for (int j = 0; j < CPT; j++) {
                float dt_ = dtv[j][s], xc_ = xcv[j][s];
                float dtx = dt_ * xc_;
                ull dt2 = pk2(dt_, dt_), dtx2 = pk2(dtx, dtx);
#pragma unroll
                for (int p = 0; p < 2; p++) {
                    ull w = mul2_(dt2, ALn[j][p]);
                    ull e = fma2_(w, k24, k6);
                    e = fma2_(e, w, kh);
                    e = fma2_(e, w, k1);
                    e = fma2_(e, w, k1);
                    h2[j][p] = fma2_(h2[j][p], e, mul2_(B2[p], dtx2));
                }
#pragma unroll
                for (int p = 2; p < 8; p++) {
                    float2 ww = upk2(mul2_(dt2, ALe[j][p - 2]));
                    ull dA = pk2(ex2_(ww.x), ex2_(ww.y));
                    h2[j][p] = fma2_(h2[j][p], dA, mul2_(B2[p], dtx2));
                }
            }
            if (s == 0) {  // norm event (t0 % 10 == 0 always)
                ull ss2 = pk2(0.f, 0.f);
#pragma unroll
                for (int j = 0; j < CPT; j++)
#pragma unroll
                    for (int p = 0; p < 8; p++) ss2 = fma2_(h2[j][p], h2[j][p], ss2);
                float2 sp = upk2(ss2);
                float ss = sp.x + sp.y;
#pragma unroll
                for (int o = 16; o; o >>= 1) ss += __shfl_xor_sync(0xffffffffu, ss, o);
                if (lane == 0) warp_part[wid] = ss;
                __syncthreads();
                int par = c & 1;
                if (wid == 0) {
                    float v = warp_part[lane & 3];
                    v += __shfl_xor_sync(0xffffffffu, v, 1);
                    v += __shfl_xor_sync(0xffffffffu, v, 2);
                    if (lane < cs) {
                        uint32_t myslot = slot_u32 + (uint32_t)((par * 16 + (int)rank) * 4);
                        ST_REMOTE_F32(myslot, (uint32_t)lane, v);
                        MBAR_ARRIVE_REMOTE(mbar_u32, (uint32_t)lane);
                    }
                    MBAR_WAIT_CLU(mbar_u32, (uint32_t)(c & 1));
                    float w = (lane < cs) ? slotbuf[par][lane] : 0.f;
                    w += __shfl_xor_sync(0xffffffffu, w, 8);
                    w += __shfl_xor_sync(0xffffffffu, w, 4);
                    w += __shfl_xor_sync(0xffffffffu, w, 2);
                    w += __shfl_xor_sync(0xffffffffu, w, 1);
                    if (lane == 0) s_fac = fminf(20.f / (sqrtf(w) + 1e-8f), 1.f);
                }
                __syncthreads();
                float fac = s_fac;
                ull fac2 = pk2(fac, fac);
#pragma unroll
                for (int j = 0; j < CPT; j++)
#pragma unroll
                    for (int p = 0; p < 8; p++) h2[j][p] = mul2_(h2[j][p], fac2);
            }
#pragma unroll
            for (int j = 0; j < CPT; j++) {
                ull y2 = pk2(Dv[j] * xcv[j][s], 0.f);
#pragma unroll
                for (int p = 0; p < 8; p++) y2 = fma2_(h2[j][p], C2[p], y2);
                float2 yy = upk2(y2);
                float gated = (yy.x + yy.y) * sgv[j][s] * S_G;
                g8_base[(size_t)(t0 + s) * DI + j * 128 + tid] =
                    (uint8_t)(qe4x2(0.f, gated) & 0xffu);
            }
        }
    };

    for (int c = 0; c <= 102; c++) {
        if (c < 102) { stage(c + 1); CP_WAIT(1); }
        else         { CP_WAIT(0); }
        __syncthreads();
        if (c < 102) chunk_body(c, std::integral_constant<int, 10>{});
        else         chunk_body(c, std::integral_constant<int, 4>{});
    }
}

// ------------------------- launch -------------------------
extern "C" void kernel_launch(void* const* d_in, const int* in_sizes, int n_in,
                              void* d_out, int out_size)
{
    const float* x       = (const float*)d_in[0];
    const float* norm_w  = (const float*)d_in[1];
    const float* W_in    = (const float*)d_in[2];
    const float* conv_w  = (const float*)d_in[3];
    const float* conv_b  = (const float*)d_in[4];
    const float* W_dt    = (const float*)d_in[5];
    const float* b_dt    = (const float*)d_in[6];
    const float* W_B     = (const float*)d_in[7];
    const float* W_C     = (const float*)d_in[8];
    const float* A_log   = (const float*)d_in[9];
    const float* D_param = (const float*)d_in[10];
    const float* W_out   = (const float*)d_in[11];
    const float* r_scale = (const float*)d_in[12];
    float* out = (float*)d_out;

    void *p_dt, *p_xn8, *p_xc8, *p_g8, *p_wi8, *p_wd8, *p_wo8;
    cudaGetSymbolAddress(&p_dt, g_dt);
    cudaGetSymbolAddress(&p_xn8, g_xn8);
    cudaGetSymbolAddress(&p_xc8, g_xc8);
    cudaGetSymbolAddress(&p_g8, g_g8);
    cudaGetSymbolAddress(&p_wi8, g_Win8);
    cudaGetSymbolAddress(&p_wd8, g_Wdt8);
    cudaGetSymbolAddress(&p_wo8, g_Wout8);

    static cudaStream_t sA = nullptr, sB2 = nullptr;
    static cudaEvent_t ev[6] = {};
    if (!sA) {
        cudaStreamCreateWithFlags(&sA, cudaStreamNonBlocking);
        cudaStreamCreateWithFlags(&sB2, cudaStreamNonBlocking);
        for (int i = 0; i < 6; i++) cudaEventCreateWithFlags(&ev[i], cudaEventDisableTiming);
    }

    // fork sA for weight conversions
    cudaEventRecord(ev[0], 0);
    cudaStreamWaitEvent(sA, ev[0], 0);
    cvt_w8_kernel<<<(2 * DI * DM / 8) / 256, 256, 0, sA>>>(W_in, (uint8_t*)p_wi8, 2 * DI * DM / 8);
    cudaEventRecord(ev[1], sA);
    cvt_w8_kernel<<<(DI * DI / 8) / 256, 256, 0, sA>>>(W_dt, (uint8_t*)p_wd8, DI * DI / 8);
    cudaEventRecord(ev[2], sA);
    cvt_w8_kernel<<<(DM * DI / 8) / 256, 256, 0, sA>>>(W_out, (uint8_t*)p_wo8, DM * DI / 8);
    cudaEventRecord(ev[3], sA);

    // main stream
    rmsnorm_kernel<<<NTOK, 256>>>(x, norm_w);
    cudaStreamWaitEvent(0, ev[1], 0);
    gemm_fp8<0><<<dim3(4096 / 128, NTOK / 128), 256>>>(
        (const uint8_t*)p_xn8, (const uint8_t*)p_wi8,
        nullptr, 4096, 1024, DESC0, nullptr, nullptr, nullptr);
    conv_silu_kernel<<<NTOK, 256>>>(conv_w, conv_b);

    // fork bpcp in parallel with dt GEMM
    cudaEventRecord(ev[4], 0);
    cudaStreamWaitEvent(sB2, ev[4], 0);
    bpcp_kernel<<<NTOK / 4, 256, 0, sB2>>>(W_B, W_C);
    cudaEventRecord(ev[5], sB2);

    cudaStreamWaitEvent(0, ev[2], 0);
    gemm_fp8<1><<<dim3(DI / 128, NTOK / 128), 256>>>(
        (const uint8_t*)p_xc8, (const uint8_t*)p_wd8,
        (float*)p_dt, DI, DI, DESC1, b_dt, nullptr, nullptr);
    cudaStreamWaitEvent(0, ev[5], 0);

    // selective scan: cluster-16 (CPT=1) with cluster-8 (CPT=2) fallback
    {
        cudaError_t e = cudaFuncSetAttribute(
            (const void*)scan_kernel<1>,
            cudaFuncAttributeNonPortableClusterSizeAllowed, 1);
        cudaLaunchConfig_t cfg = {};
        cudaLaunchAttribute at[1];
        at[0].id = cudaLaunchAttributeClusterDimension;
        cfg.attrs = at;
        cfg.numAttrs = 1;
        cfg.blockDim = dim3(128, 1, 1);
        cfg.stream = 0;
        if (e == cudaSuccess) {
            int cs = 16;
            at[0].val.clusterDim = {16, 1, 1};
            cfg.gridDim = dim3(32, 1, 1);
            cudaLaunchKernelEx(&cfg, scan_kernel<1>, A_log, D_param, cs);
        } else {
            (void)cudaGetLastError();
            int cs = 8;
            at[0].val.clusterDim = {8, 1, 1};
            cfg.gridDim = dim3(16, 1, 1);
            cudaLaunchKernelEx(&cfg, scan_kernel<2>, A_log, D_param, cs);
        }
    }

    cudaStreamWaitEvent(0, ev[3], 0);
    gemm_fp8<2><<<dim3(DM / 128, NTOK / 128), 256>>>(
        (const uint8_t*)p_g8, (const uint8_t*)p_wo8,
        out, DM, DI, DESC2, nullptr, x, r_scale);
}